// round 13
// baseline (speedup 1.0000x reference)
#include <cuda_runtime.h>
#include <math.h>

// ---------------- static scratch (no allocation allowed) ----------------
#define N_MAX 150016
#define E_MAX 900032

__device__ float g_y[(size_t)N_MAX * 256];   // GEMM output (pre-BN), per-layer ld
__device__ float g_z[(size_t)N_MAX * 96];    // aggregated input features
__device__ float g_x[(size_t)N_MAX * 128];   // fc0 output
__device__ int   g_deg[N_MAX];
__device__ int   g_cursor[N_MAX];
__device__ int   g_rowptr[N_MAX + 1];        // block-local exclusive scan
__device__ int2  g_csr[E_MAX];               // (src, weight-bits) fused meta
__device__ float g_dinv[N_MAX];
__device__ float g_cs[N_MAX];
__device__ int   g_blocksum[256];
__device__ int   g_blockoff[257];
__device__ float g_sumL[5 * 256];            // per-layer BN sum slots
__device__ float g_sqL[5 * 256];             // per-layer BN sumsq slots
__device__ float g_pool[64 * 128];

// ---------------- f32x2 helpers ----------------
__device__ __forceinline__ void fma2(unsigned long long& acc,
                                     unsigned long long a, unsigned long long b) {
    asm("fma.rn.f32x2 %0, %1, %2, %0;" : "+l"(acc) : "l"(a), "l"(b));
}
__device__ __forceinline__ unsigned long long pack2(float lo, float hi) {
    unsigned long long r;
    asm("mov.b64 %0, {%1, %2};" : "=l"(r) : "f"(lo), "f"(hi));
    return r;
}
__device__ __forceinline__ float2 unpack2(unsigned long long v) {
    float2 r;
    asm("mov.b64 {%0, %1}, %2;" : "=f"(r.x), "=f"(r.y) : "l"(v));
    return r;
}

// inline BN coeff from per-layer stat slot
__device__ __forceinline__ void bn_coeff(int slot, int c, float invM,
                                         const float* __restrict__ gamma,
                                         const float* __restrict__ beta,
                                         float& s, float& h) {
    float mean = g_sumL[slot * 256 + c] * invM;
    float var = g_sqL[slot * 256 + c] * invM - mean * mean;
    float r = rsqrtf(var + 1e-5f);
    s = gamma[c] * r;
    h = beta[c] - mean * s;
}

// ---------------- prep kernels ----------------
__global__ void k_zero(int n) {
    int i = blockIdx.x * blockDim.x + threadIdx.x;
    if (i < n) { g_deg[i] = 0; g_cursor[i] = 0; }
    if (i < 5 * 256) { g_sumL[i] = 0.f; g_sqL[i] = 0.f; }
    if (i < 64 * 128) g_pool[i] = 0.f;
}

__global__ void k_hist(const int* __restrict__ dst, int e) {
    int i = blockIdx.x * blockDim.x + threadIdx.x;
    if (i < e) atomicAdd(&g_deg[dst[i]], 1);
}

__global__ void k_scan1(int n) {
    __shared__ int sh[1024];
    int t = threadIdx.x;
    int idx = blockIdx.x * 1024 + t;
    int v = (idx < n) ? g_deg[idx] : 0;
    sh[t] = v;
    __syncthreads();
    for (int off = 1; off < 1024; off <<= 1) {
        int add = (t >= off) ? sh[t - off] : 0;
        __syncthreads();
        sh[t] += add;
        __syncthreads();
    }
    if (idx < n) {
        g_rowptr[idx] = sh[t] - v;
        float d = (float)(v + 1);
        float r = rsqrtf(d);
        g_dinv[idx] = r;
        g_cs[idx] = r * r;
    }
    if (t == 1023) g_blocksum[blockIdx.x] = sh[t];
}

__global__ void k_scan2(int nb, int n) {
    __shared__ int sh[256];
    int t = threadIdx.x;
    int v = (t < nb) ? g_blocksum[t] : 0;
    sh[t] = v;
    __syncthreads();
    for (int off = 1; off < 256; off <<= 1) {
        int add = (t >= off) ? sh[t - off] : 0;
        __syncthreads();
        sh[t] += add;
        __syncthreads();
    }
    int total = sh[255];
    if (t < nb) g_blockoff[t] = sh[t] - v;
    if (t == nb) g_blockoff[nb] = total;
    if (t == (n >> 10)) g_rowptr[n] = total - (sh[t] - v);
}

__device__ __forceinline__ int rp(int i) {
    return g_rowptr[i] + g_blockoff[i >> 10];
}

__global__ void k_place(const int* __restrict__ src, const int* __restrict__ dst, int e) {
    int i = blockIdx.x * blockDim.x + threadIdx.x;
    if (i < e) {
        int d = dst[i], s = src[i];
        int p = rp(d) + atomicAdd(&g_cursor[d], 1);
        float w = g_dinv[s] * g_dinv[d];
        g_csr[p] = make_int2(s, __float_as_int(w));
    }
}

// ---------------- aggregation: warp/node, 2-deep pipelined meta loads -------
// MODE 0: input = xext (raw pos). MODE 1: input = relu(bn(g_y)), bn inline
// from stat slot `prev` + gamma/beta. ldin/ldout allow padded strides.
template<int MODE>
__global__ void k_agg(const float* __restrict__ xext,
                      const float* __restrict__ gamma, const float* __restrict__ beta,
                      int prev, int n, int din, int ldin, int ldout) {
    const float* __restrict__ x = (MODE == 0) ? xext : g_y;
    int gt = blockIdx.x * blockDim.x + threadIdx.x;
    int node = gt >> 5;
    int lane = gt & 31;
    if (node >= n) return;
    int c0 = lane, c1 = lane + 32, c2 = lane + 64;
    bool v0 = c0 < din, v1 = c1 < din, v2 = c2 < din;
    float s0 = 1.f, h0 = 0.f, s1 = 1.f, h1 = 0.f, s2 = 1.f, h2 = 0.f;
    if (MODE) {
        float invM = 1.f / (float)n;
        if (v0) bn_coeff(prev, c0, invM, gamma, beta, s0, h0);
        if (v1) bn_coeff(prev, c1, invM, gamma, beta, s1, h1);
        if (v2) bn_coeff(prev, c2, invM, gamma, beta, s2, h2);
    }
    int beg = rp(node), end = rp(node + 1);
    float a0 = 0.f, a1 = 0.f, a2 = 0.f;
    int2 m0 = (beg < end)     ? g_csr[beg]     : make_int2(0, 0);
    int2 m1 = (beg + 1 < end) ? g_csr[beg + 1] : make_int2(0, 0);
    for (int p = beg; p < end; p += 2) {
        int e0 = m0.x; float w0 = __int_as_float(m0.y);
        int e1 = m1.x; float w1 = __int_as_float(m1.y);
        m0 = (p + 2 < end) ? g_csr[p + 2] : make_int2(0, 0);
        m1 = (p + 3 < end) ? g_csr[p + 3] : make_int2(0, 0);
        const float* xa = x + (size_t)e0 * ldin;
        const float* xb = x + (size_t)e1 * ldin;
        float p0a = 0.f, p1a = 0.f, p2a = 0.f, p0b = 0.f, p1b = 0.f, p2b = 0.f;
        if (v0) { p0a = xa[c0]; p0b = xb[c0]; }
        if (v1) { p1a = xa[c1]; p1b = xb[c1]; }
        if (v2) { p2a = xa[c2]; p2b = xb[c2]; }
        if (MODE) {
            if (v0) { p0a = fmaxf(fmaf(p0a, s0, h0), 0.f); p0b = fmaxf(fmaf(p0b, s0, h0), 0.f); }
            if (v1) { p1a = fmaxf(fmaf(p1a, s1, h1), 0.f); p1b = fmaxf(fmaf(p1b, s1, h1), 0.f); }
            if (v2) { p2a = fmaxf(fmaf(p2a, s2, h2), 0.f); p2b = fmaxf(fmaf(p2b, s2, h2), 0.f); }
        }
        if (v0) { a0 = fmaf(p0a, w0, a0); a0 = fmaf(p0b, w1, a0); }
        if (v1) { a1 = fmaf(p1a, w0, a1); a1 = fmaf(p1b, w1, a1); }
        if (v2) { a2 = fmaf(p2a, w0, a2); a2 = fmaf(p2b, w1, a2); }
    }
    float cw = g_cs[node];
    const float* xi = x + (size_t)node * ldin;
    float* zi = g_z + (size_t)node * ldout;
    if (v0) { float v = xi[c0]; if (MODE) v = fmaxf(fmaf(v, s0, h0), 0.f); zi[c0] = fmaf(v, cw, a0); }
    if (v1) { float v = xi[c1]; if (MODE) v = fmaxf(fmaf(v, s1, h1), 0.f); zi[c1] = fmaf(v, cw, a1); }
    if (v2) { float v = xi[c2]; if (MODE) v = fmaxf(fmaf(v, s2, h2), 0.f); zi[c2] = fmaf(v, cw, a2); }
}

// ---------------- small GEMM (K<=16, NC<=32): thread per row, stats->slot ----
template<int K, int NC>
__global__ __launch_bounds__(256) void k_gemm_s(
    const float* __restrict__ Bm, const float* __restrict__ bias, int M, int slot)
{
    __shared__ float Ws[K * NC];
    __shared__ float bs[NC];
    int tid = threadIdx.x;
    for (int i = tid; i < K * NC; i += 256) Ws[i] = Bm[i];
    if (tid < NC) bs[tid] = bias[tid];
    __syncthreads();

    int r = blockIdx.x * 256 + tid;
    bool valid = r < M;
    float a[K];
    #pragma unroll
    for (int k = 0; k < K; k++) a[k] = valid ? g_z[(size_t)r * K + k] : 0.f;
    float acc[NC];
    #pragma unroll
    for (int c = 0; c < NC; c++) acc[c] = valid ? bs[c] : 0.f;
    #pragma unroll
    for (int k = 0; k < K; k++)
        #pragma unroll
        for (int c = 0; c < NC; c++) acc[c] = fmaf(a[k], Ws[k * NC + c], acc[c]);

    if (valid) {
        float4* dst = (float4*)(g_y + (size_t)r * NC);
        #pragma unroll
        for (int c = 0; c < NC; c += 4)
            dst[c >> 2] = make_float4(acc[c], acc[c + 1], acc[c + 2], acc[c + 3]);
    }
    float q[NC];
    #pragma unroll
    for (int c = 0; c < NC; c++) q[c] = acc[c] * acc[c];
    #pragma unroll
    for (int off = 16; off; off >>= 1) {
        #pragma unroll
        for (int c = 0; c < NC; c++) {
            acc[c] += __shfl_down_sync(0xffffffffu, acc[c], off);
            q[c]   += __shfl_down_sync(0xffffffffu, q[c], off);
        }
    }
    if ((tid & 31) == 0) {
        #pragma unroll
        for (int c = 0; c < NC; c++) {
            atomicAdd(&g_sumL[slot * 256 + c], acc[c]);
            atomicAdd(&g_sqL[slot * 256 + c], q[c]);
        }
    }
}

// ---------------- f32x2 tiled SGEMM: BLKM x BLKN, 256 threads, 8x8/thread ----
// FC0==0: g_y = g_z @ W + b (stats -> slot).
// FC0==1: g_x = relu( relu(bn_prev(g_y)) @ W + b ), bn inline from prev slot.
template<int BLKM, int BLKN, int FC0>
__global__ __launch_bounds__(256, 2) void k_gemm2(
    const float* __restrict__ Bm, const float* __restrict__ bias,
    int M, int K, int Nc, int lda, int ldc, int slot,
    const float* __restrict__ gamma, const float* __restrict__ beta, int prev)
{
    constexpr int NTX = BLKN / 8;
    constexpr int NTY = 256 / NTX;
    constexpr int NLA = BLKM / 16;
    constexpr int ASZ = 16 * (BLKM + 4) * 4;
    constexpr int BSZ = 16 * BLKN * 4;
    constexpr int RSZ = NTY * BLKN * 8;
    constexpr int SMSZ = (ASZ + BSZ) > RSZ ? (ASZ + BSZ) : RSZ;
    const float* __restrict__ A = FC0 ? g_y : g_z;
    float* __restrict__ C = FC0 ? g_x : g_y;

    __shared__ __align__(16) char smraw[SMSZ];
    float* As = (float*)smraw;
    float* Bs = (float*)(smraw + ASZ);
    float2* red2 = (float2*)smraw;
    __shared__ float sbn_s[256], sbn_h[256];

    int tid = threadIdx.x;
    int tx = tid % NTX;
    int tr = tid / NTX;
    int row0 = blockIdx.y * BLKM;
    int col0 = blockIdx.x * BLKN;

    if (FC0) {
        float invM = 1.f / (float)M;
        for (int i = tid; i < K; i += 256) {
            float s, h;
            bn_coeff(prev, i, invM, gamma, beta, s, h);
            sbn_s[i] = s; sbn_h[i] = h;
        }
        __syncthreads();
    }

    unsigned long long acc[8][4];
    #pragma unroll
    for (int i = 0; i < 8; i++)
        #pragma unroll
        for (int j = 0; j < 4; j++) acc[i][j] = 0ull;

    int la_k = tid & 15, la_r = tid >> 4;
    int lb_k0 = tid / BLKN, lb_n = tid % BLKN;
    constexpr int LBSTEP = 256 / BLKN;

    for (int k0 = 0; k0 < K; k0 += 16) {
        #pragma unroll
        for (int j = 0; j < NLA; j++) {
            int r = la_r + j * 16;
            int gk = k0 + la_k;
            float v = 0.f;
            if (row0 + r < M && gk < K) {
                v = A[(size_t)(row0 + r) * lda + gk];
                if (FC0) v = fmaxf(fmaf(v, sbn_s[gk], sbn_h[gk]), 0.f);
            }
            As[la_k * (BLKM + 4) + r] = v;
        }
        #pragma unroll
        for (int kk = lb_k0; kk < 16; kk += LBSTEP) {
            int gk = k0 + kk, c = col0 + lb_n;
            Bs[kk * BLKN + lb_n] = (gk < K && c < Nc) ? Bm[(size_t)gk * Nc + c] : 0.f;
        }
        __syncthreads();
        #pragma unroll
        for (int kk = 0; kk < 16; kk++) {
            float4 aLo = *(const float4*)&As[kk * (BLKM + 4) + tr * 8];
            float4 aHi = *(const float4*)&As[kk * (BLKM + 4) + tr * 8 + 4];
            unsigned long long a2[8];
            a2[0] = pack2(aLo.x, aLo.x); a2[1] = pack2(aLo.y, aLo.y);
            a2[2] = pack2(aLo.z, aLo.z); a2[3] = pack2(aLo.w, aLo.w);
            a2[4] = pack2(aHi.x, aHi.x); a2[5] = pack2(aHi.y, aHi.y);
            a2[6] = pack2(aHi.z, aHi.z); a2[7] = pack2(aHi.w, aHi.w);
            unsigned long long b2[4];
            #pragma unroll
            for (int j = 0; j < 4; j++)
                b2[j] = *(const unsigned long long*)&Bs[kk * BLKN + 2 * tx + 2 * NTX * j];
            #pragma unroll
            for (int i = 0; i < 8; i++)
                #pragma unroll
                for (int j = 0; j < 4; j++)
                    fma2(acc[i][j], a2[i], b2[j]);
        }
        __syncthreads();
    }

    #pragma unroll
    for (int j = 0; j < 4; j++) {
        int lc = 2 * tx + 2 * NTX * j;
        int c = col0 + lc;
        float b0 = (c < Nc) ? bias[c] : 0.f;
        float b1 = (c + 1 < Nc) ? bias[c + 1] : 0.f;
        float s0 = 0.f, q0 = 0.f, s1 = 0.f, q1 = 0.f;
        #pragma unroll
        for (int i = 0; i < 8; i++) {
            int r = row0 + tr * 8 + i;
            float2 v = unpack2(acc[i][j]);
            v.x += b0; v.y += b1;
            if (FC0) { v.x = fmaxf(v.x, 0.f); v.y = fmaxf(v.y, 0.f); }
            if (r < M) {
                if (c < Nc)     C[(size_t)r * ldc + c] = v.x;
                if (c + 1 < Nc) C[(size_t)r * ldc + c + 1] = v.y;
                s0 += v.x; q0 = fmaf(v.x, v.x, q0);
                s1 += v.y; q1 = fmaf(v.y, v.y, q1);
            }
        }
        if (!FC0) {
            red2[tr * BLKN + lc]     = make_float2(s0, q0);
            red2[tr * BLKN + lc + 1] = make_float2(s1, q1);
        }
    }
    if (!FC0) {
        __syncthreads();
        if (tr == 0) {
            #pragma unroll
            for (int j = 0; j < 4; j++) {
                #pragma unroll
                for (int h = 0; h < 2; h++) {
                    int lc = 2 * tx + 2 * NTX * j + h;
                    float s = 0.f, q = 0.f;
                    for (int u = 0; u < NTY; u++) {
                        float2 t = red2[u * BLKN + lc];
                        s += t.x; q += t.y;
                    }
                    int c = col0 + lc;
                    if (c < Nc) {
                        atomicAdd(&g_sumL[slot * 256 + c], s);
                        atomicAdd(&g_sqL[slot * 256 + c], q);
                    }
                }
            }
        }
    }
}

// ---------------- parallel segment max: relu + atomicMax on bits -----------
__global__ void k_segmax2(const int* __restrict__ batch, int n) {
    int c = threadIdx.x;
    int rows_per = (n + gridDim.x - 1) / gridDim.x;
    int r0 = blockIdx.x * rows_per;
    int r1 = min(n, r0 + rows_per);
    if (r0 >= r1) return;
    int g = batch[r0];
    float m = 0.f;
    for (int r = r0; r < r1; r++) {
        int gr = batch[r];
        if (gr != g) {
            atomicMax((int*)&g_pool[g * 128 + c], __float_as_int(m));
            g = gr; m = 0.f;
        }
        m = fmaxf(m, g_x[(size_t)r * 128 + c]);
    }
    atomicMax((int*)&g_pool[g * 128 + c], __float_as_int(m));
}

__global__ void k_head(const float* __restrict__ W1, const float* __restrict__ b1,
                       const float* __restrict__ W2, const float* __restrict__ b2,
                       const float* __restrict__ W3, const float* __restrict__ b3,
                       float* __restrict__ out) {
    __shared__ float xs[128];
    __shared__ float red[128];
    int g = blockIdx.x, c = threadIdx.x;
    xs[c] = g_pool[g * 128 + c];
    __syncthreads();

    float v = b1[c];
    #pragma unroll 8
    for (int k = 0; k < 128; k++) v = fmaf(xs[k], W1[k * 128 + c], v);
    v = fmaxf(v, 0.f);
    __syncthreads(); xs[c] = v; __syncthreads();

    v = b2[c];
    #pragma unroll 8
    for (int k = 0; k < 128; k++) v = fmaf(xs[k], W2[k * 128 + c], v);
    v = fmaxf(v, 0.f);
    __syncthreads(); xs[c] = v; __syncthreads();

    float v3 = b3[c];
    #pragma unroll 8
    for (int k = 0; k < 128; k++) v3 = fmaf(xs[k], W3[k * 128 + c], v3);

    red[c] = v3 * v3;
    __syncthreads();
    for (int off = 64; off > 0; off >>= 1) {
        if (c < off) red[c] += red[c + off];
        __syncthreads();
    }
    float nrm = fmaxf(sqrtf(red[0]), 1e-12f);
    out[g * 128 + c] = v3 / nrm;
}

// ---------------- host launch: kernel launches ONLY ----------------
extern "C" void kernel_launch(void* const* d_in, const int* in_sizes, int n_in,
                              void* d_out, int out_size) {
    const float* pos = (const float*)d_in[0];
    const int* ei = (const int*)d_in[1];
    const int* batch = (const int*)d_in[2];
    int n = in_sizes[0] / 3;
    int e = in_sizes[1] / 2;
    const int* src = ei;
    const int* dst = ei + e;
    float* out = (float*)d_out;

    const float *W[5], *bb[5], *gg[5], *be[5];
    for (int l = 0; l < 5; l++) {
        W[l]  = (const float*)d_in[3 + 4 * l];
        bb[l] = (const float*)d_in[4 + 4 * l];
        gg[l] = (const float*)d_in[5 + 4 * l];
        be[l] = (const float*)d_in[6 + 4 * l];
    }
    const float* fc0_W = (const float*)d_in[23];
    const float* fc0_b = (const float*)d_in[24];
    const float* fc1_W = (const float*)d_in[25];
    const float* fc1_b = (const float*)d_in[26];
    const float* fc2_W = (const float*)d_in[27];
    const float* fc2_b = (const float*)d_in[28];
    const float* fc3_W = (const float*)d_in[29];
    const float* fc3_b = (const float*)d_in[30];

    // ---- graph preprocessing ----
    k_zero<<<(n + 255) / 256, 256>>>(n);
    k_hist<<<(e + 255) / 256, 256>>>(dst, e);
    int nb = (n + 1023) / 1024;
    k_scan1<<<nb, 1024>>>(n);
    k_scan2<<<1, 256>>>(nb, n);
    k_place<<<(e + 255) / 256, 256>>>(src, dst, e);

    int aggBlocks = (n + 7) / 8;
    int rb128 = (n + 127) / 128;
    int rb256 = (n + 255) / 256;

    // ---- layer 1: 3 -> 16 (stats slot 0) ----
    k_agg<0><<<aggBlocks, 256>>>(pos, nullptr, nullptr, 0, n, 3, 3, 3);
    k_gemm_s<3, 16><<<(n + 255) / 256, 256>>>(W[0], bb[0], n, 0);

    // ---- layer 2: 16 -> 32 (prev slot 0 -> stats slot 1) ----
    k_agg<1><<<aggBlocks, 256>>>(nullptr, gg[0], be[0], 0, n, 16, 16, 16);
    k_gemm_s<16, 32><<<(n + 255) / 256, 256>>>(W[1], bb[1], n, 1);

    // ---- layer 3: 32 -> 64 (prev 1 -> slot 2) ----
    k_agg<1><<<aggBlocks, 256>>>(nullptr, gg[1], be[1], 1, n, 32, 32, 32);
    k_gemm2<256, 64, 0><<<dim3(1, rb256), 256>>>(W[2], bb[2], n, 32, 64, 32, 64, 2, nullptr, nullptr, 0);

    // ---- layer 4: 64 -> 94 (prev 2 -> slot 3), ldc padded to 96 ----
    k_agg<1><<<aggBlocks, 256>>>(nullptr, gg[2], be[2], 2, n, 64, 64, 64);
    k_gemm2<256, 64, 0><<<dim3(2, rb256), 256>>>(W[3], bb[3], n, 64, 94, 64, 96, 3, nullptr, nullptr, 0);

    // ---- layer 5: 94 -> 256 (prev 3 -> slot 4), strides 96 ----
    k_agg<1><<<aggBlocks, 256>>>(nullptr, gg[3], be[3], 3, n, 94, 96, 96);
    k_gemm2<128, 128, 0><<<dim3(2, rb128), 256>>>(W[4], bb[4], n, 94, 256, 96, 256, 4, nullptr, nullptr, 0);

    // ---- fc0: relu(bn4(g_y)) @ W (256 -> 128), bn inline from slot 4 ----
    k_gemm2<128, 128, 1><<<dim3(1, rb128), 256>>>(fc0_W, fc0_b, n, 256, 128, 256, 128, 0, gg[4], be[4], 4);

    // ---- parallel segment max pool + head MLP + normalize ----
    k_segmax2<<<1024, 128>>>(batch, n);
    k_head<<<64, 128>>>(fc1_W, fc1_b, fc2_W, fc2_b, fc3_W, fc3_b, out);
}